// round 12
// baseline (speedup 1.0000x reference)
#include <cuda_runtime.h>
#include <cuda_fp16.h>
#include <cstdint>
#include <math.h>

#define T_TOK 4096
#define H_DIM 2048
#define I_DIM 768
#define E_NUM 8

// ---- scratch (device globals; no allocation allowed) ----
__device__ int    g_cnt[E_NUM];
__device__ int    g_tok[E_NUM * T_TOK];
__device__ float  g_wt [E_NUM * T_TOK];
__device__ __half g_acth[(size_t)E_NUM * T_TOK * I_DIM];

// ============================ helpers ====================================
__device__ __forceinline__ uint32_t smem_u32(const void* p) {
    uint32_t a;
    asm("{ .reg .u64 t; cvta.to.shared.u64 t, %1; cvt.u32.u64 %0, t; }" : "=r"(a) : "l"(p));
    return a;
}
__device__ __forceinline__ void ldm_x4(uint32_t* r, uint32_t a) {
    asm volatile("ldmatrix.sync.aligned.m8n8.x4.shared.b16 {%0,%1,%2,%3}, [%4];"
                 : "=r"(r[0]), "=r"(r[1]), "=r"(r[2]), "=r"(r[3]) : "r"(a));
}
__device__ __forceinline__ void ldm_x4_t(uint32_t* r, uint32_t a) {
    asm volatile("ldmatrix.sync.aligned.m8n8.x4.trans.shared.b16 {%0,%1,%2,%3}, [%4];"
                 : "=r"(r[0]), "=r"(r[1]), "=r"(r[2]), "=r"(r[3]) : "r"(a));
}
__device__ __forceinline__ void mma16816(float* c, const uint32_t* a, uint32_t b0, uint32_t b1) {
    asm volatile("mma.sync.aligned.m16n8k16.row.col.f32.f16.f16.f32 "
                 "{%0,%1,%2,%3}, {%4,%5,%6,%7}, {%8,%9}, {%0,%1,%2,%3};"
                 : "+f"(c[0]), "+f"(c[1]), "+f"(c[2]), "+f"(c[3])
                 : "r"(a[0]), "r"(a[1]), "r"(a[2]), "r"(a[3]), "r"(b0), "r"(b1));
}
// convert 8 fp32 -> 8 fp16 (packed uint4)
__device__ __forceinline__ void cvt8(float4 a, float4 b, uint4& H) {
    __half2 h0 = __floats2half2_rn(a.x, a.y);
    __half2 h1 = __floats2half2_rn(a.z, a.w);
    __half2 h2 = __floats2half2_rn(b.x, b.y);
    __half2 h3 = __floats2half2_rn(b.z, b.w);
    H.x = *(uint32_t*)&h0; H.y = *(uint32_t*)&h1;
    H.z = *(uint32_t*)&h2; H.w = *(uint32_t*)&h3;
}

// ---------------------------------------------------------------------------
__global__ void k_init() { if (threadIdx.x < E_NUM) g_cnt[threadIdx.x] = 0; }

// ---------------------------------------------------------------------------
__global__ void k_router(const float* __restrict__ x, const float* __restrict__ wr,
                         float* __restrict__ out_logits, int write_logits) {
    int warp = threadIdx.x >> 5, lane = threadIdx.x & 31;
    int t = blockIdx.x * 8 + warp;
    if (t >= T_TOK) return;
    float acc[E_NUM];
#pragma unroll
    for (int e = 0; e < E_NUM; e++) acc[e] = 0.f;
    const float* xp = x + (size_t)t * H_DIM;
    for (int h = lane; h < H_DIM; h += 32) {
        float xv = xp[h];
        const float* w = wr + (size_t)h * E_NUM;
#pragma unroll
        for (int e = 0; e < E_NUM; e++) acc[e] += xv * w[e];
    }
#pragma unroll
    for (int e = 0; e < E_NUM; e++)
#pragma unroll
        for (int o = 16; o > 0; o >>= 1)
            acc[e] += __shfl_xor_sync(0xffffffffu, acc[e], o);
    if (lane == 0) {
        if (write_logits)
#pragma unroll
            for (int e = 0; e < E_NUM; e++)
                out_logits[(size_t)t * E_NUM + e] = acc[e];
        int i1 = 0;
#pragma unroll
        for (int e = 1; e < E_NUM; e++) if (acc[e] > acc[i1]) i1 = e;
        int i2 = (i1 == 0) ? 1 : 0;
#pragma unroll
        for (int e = 0; e < E_NUM; e++)
            if (e != i1 && acc[e] > acc[i2]) i2 = e;
        float p2 = expf(acc[i2] - acc[i1]);
        float w1 = 1.f / (1.f + p2), w2 = p2 * w1;
        int p;
        p = atomicAdd(&g_cnt[i1], 1);
        g_tok[i1 * T_TOK + p] = t; g_wt[i1 * T_TOK + p] = w1;
        p = atomicAdd(&g_cnt[i2], 1);
        g_tok[i2 * T_TOK + p] = t; g_wt[i2 * T_TOK + p] = w2;
    }
}

// ---------------------------------------------------------------------------
// GEMM geometry: BM=128, BN=128, BK=16, 128 thr, warps 2(M)x2(N), warp 64x64.
// 2 CTAs/SM. Single-pass fp16 (fp32 accumulate). Static smem, 3 stages x
// 8192B: A 4K | B 4K. 1 sync/iter. A rows 32B, swizzle off^(((row>>2)&1)<<4);
// B rows 256B (16 n8 units), swizzle ^((k&7)) on 16B-unit index.
#define STAGE_B 8192

#define COMPUTE_STAGE(SB0)                                                    \
    do {                                                                      \
        uint32_t Af[4][4];                                                    \
        _Pragma("unroll")                                                     \
        for (int i = 0; i < 4; i++) {                                         \
            int row = arow_l + i * 16;                                        \
            uint32_t ad = (SB0) + row * 32 +                                  \
                          (acol_l ^ ((((uint32_t)row >> 2) & 1) << 4));       \
            ldm_x4(Af[i], ad);                                                \
        }                                                                     \
        _Pragma("unroll")                                                     \
        for (int jj = 0; jj < 4; jj++) {                                      \
            uint32_t Bf[4];                                                   \
            uint32_t nat = (uint32_t)(bnat_l + jj * 2);                       \
            uint32_t bd = (SB0) + 4096 + bk_l * 256 +                         \
                          ((nat ^ ((uint32_t)bk_l & 7)) << 4);                \
            ldm_x4_t(Bf, bd);                                                 \
            _Pragma("unroll")                                                 \
            for (int i = 0; i < 4; i++) {                                     \
                mma16816(c[i][jj * 2],     Af[i], Bf[0], Bf[1]);              \
                mma16816(c[i][jj * 2 + 1], Af[i], Bf[2], Bf[3]);              \
            }                                                                 \
        }                                                                     \
    } while (0)

// GEMM1: per expert, [Ne,H] x [H, 64 gate + 64 up interleaved by 8] -> act
__global__ __launch_bounds__(128, 2)
void k_mlp1(const float* __restrict__ x,
            const float* __restrict__ wi0, const float* __restrict__ wi1) {
    __shared__ __align__(16) char sm[3][STAGE_B];
    int e  = blockIdx.z;
    int ne = g_cnt[e];
    int m0 = blockIdx.x * 128;
    if (m0 >= ne) return;
    int i0 = blockIdx.y * 64;   // I columns [i0, i0+64)

    int tid = threadIdx.x, lane = tid & 31, wid = tid >> 5;
    int warpM = (wid >> 1) * 64, warpN = (wid & 1) * 64;
    uint32_t sbase = smem_u32(sm);

    // A fill: thread = row (0..127), 16 fp32 -> 16 fp16 (gathered token rows)
    int ar = tid;
    uint32_t asw0 = (uint32_t)(ar * 32) + ((0u)  ^ ((((uint32_t)ar >> 2) & 1) << 4));
    uint32_t asw1 = (uint32_t)(ar * 32) + ((16u) ^ ((((uint32_t)ar >> 2) & 1) << 4));
    bool av = (m0 + ar) < ne;
    const float* axp = x;
    if (av) axp = x + (size_t)g_tok[e * T_TOK + m0 + ar] * H_DIM;

    // B fill: thread handles k-row bkk = tid>>3, units natp (wi0) & natp+1 (wi1)
    int bkk = tid >> 3;           // 0..15
    int natp = (tid & 7) * 2;     // even unit
    uint32_t bsw0 = (uint32_t)(bkk * 256) + ((uint32_t)((natp)     ^ (bkk & 7)) << 4);
    uint32_t bsw1 = (uint32_t)(bkk * 256) + ((uint32_t)((natp + 1) ^ (bkk & 7)) << 4);
    size_t wsel = (size_t)e * H_DIM * I_DIM + (size_t)bkk * I_DIM + i0 + (natp >> 1) * 8;
    const float* bwp0 = wi0 + wsel;
    const float* bwp1 = wi1 + wsel;

    float c[4][8][4];
#pragma unroll
    for (int i = 0; i < 4; i++)
#pragma unroll
        for (int j = 0; j < 8; j++)
#pragma unroll
            for (int q = 0; q < 4; q++) c[i][j][q] = 0.f;

    float4 pa0, pa1, pa2, pa3, pb0a, pb0b, pb1a, pb1b;
#define LDG1(K0) do {                                                        \
    if (av) { pa0 = *(const float4*)(axp + (size_t)(K0));                    \
              pa1 = *(const float4*)(axp + (size_t)(K0) + 4);                \
              pa2 = *(const float4*)(axp + (size_t)(K0) + 8);                \
              pa3 = *(const float4*)(axp + (size_t)(K0) + 12); }             \
    else { pa0 = make_float4(0,0,0,0); pa1 = pa0; pa2 = pa0; pa3 = pa0; }    \
    pb0a = *(const float4*)(bwp0 + (size_t)(K0) * I_DIM);                    \
    pb0b = *(const float4*)(bwp0 + (size_t)(K0) * I_DIM + 4);                \
    pb1a = *(const float4*)(bwp1 + (size_t)(K0) * I_DIM);                    \
    pb1b = *(const float4*)(bwp1 + (size_t)(K0) * I_DIM + 4);                \
} while (0)
#define STS1(BUF) do {                                                       \
    char* s_ = sm[BUF];                                                      \
    uint4 H_;                                                                \
    cvt8(pa0, pa1, H_); *(uint4*)(s_ + asw0) = H_;                           \
    cvt8(pa2, pa3, H_); *(uint4*)(s_ + asw1) = H_;                           \
    cvt8(pb0a, pb0b, H_); *(uint4*)(s_ + 4096 + bsw0) = H_;                  \
    cvt8(pb1a, pb1b, H_); *(uint4*)(s_ + 4096 + bsw1) = H_;                  \
} while (0)

    LDG1(0); STS1(0);
    LDG1(16);
    __syncthreads();

    int arow_l = warpM + (lane & 15);
    uint32_t acol_l = (uint32_t)((lane >> 4) * 16);
    int bk_l = (lane & 7) + ((lane >> 3) & 1) * 8;
    int bnat_l = (warpN >> 3) + ((lane >> 4) & 1);

    const int NC = H_DIM / 16;  // 128
    for (int cc = 0; cc < NC; cc++) {
        if (cc + 1 < NC) {
            STS1((cc + 1) % 3);
            if (cc + 2 < NC) LDG1((cc + 2) * 16);
            __syncthreads();
        }
        COMPUTE_STAGE(sbase + (cc % 3) * STAGE_B);
    }
#undef LDG1
#undef STS1

    // Epilogue: accum pairs (2jj, 2jj+1) = (gate, up); silu -> fp16 act.
    int gr = lane >> 2, gc = (lane & 3) * 2;
#pragma unroll
    for (int i = 0; i < 4; i++) {
#pragma unroll
        for (int jj = 0; jj < 4; jj++) {
            int jg = jj * 2, ju = jj * 2 + 1;
            int ic = i0 + ((warpN >> 4) + jj) * 8 + gc;
#pragma unroll
            for (int hf = 0; hf < 2; hf++) {
                int slot = m0 + warpM + i * 16 + gr + hf * 8;
                if (slot < ne) {
                    float g0 = c[i][jg][2 * hf], g1 = c[i][jg][2 * hf + 1];
                    float u0 = c[i][ju][2 * hf], u1 = c[i][ju][2 * hf + 1];
                    float a0 = (g0 / (1.f + expf(-g0))) * u0;
                    float a1 = (g1 / (1.f + expf(-g1))) * u1;
                    __half2 hh = __floats2half2_rn(a0, a1);
                    size_t off = ((size_t)e * T_TOK + slot) * I_DIM + ic;
                    *(uint32_t*)(g_acth + off) = *(uint32_t*)&hh;
                }
            }
        }
    }
}

// ---------------------------------------------------------------------------
__global__ __launch_bounds__(128, 2)
void k_mlp2(const float* __restrict__ wo, float* __restrict__ out) {
    __shared__ __align__(16) char sm[3][STAGE_B];
    int e  = blockIdx.z;
    int ne = g_cnt[e];
    int m0 = blockIdx.x * 128;
    if (m0 >= ne) return;
    int n0 = blockIdx.y * 128;

    int tid = threadIdx.x, lane = tid & 31, wid = tid >> 5;
    int warpM = (wid >> 1) * 64, warpN = (wid & 1) * 64;
    uint32_t sbase = smem_u32(sm);

    // A fill: thread = row, 16 fp16 act plane (2 uint4)
    int ar = tid;
    uint32_t asw0 = (uint32_t)(ar * 32) + ((0u)  ^ ((((uint32_t)ar >> 2) & 1) << 4));
    uint32_t asw1 = (uint32_t)(ar * 32) + ((16u) ^ ((((uint32_t)ar >> 2) & 1) << 4));
    bool av = (m0 + ar) < ne;
    size_t aoff = ((size_t)e * T_TOK + m0 + ar) * I_DIM;
    const __half* ah = g_acth + aoff;

    // B fill: k-row bkk = tid>>3, units natp, natp+1 (16 consecutive H cols)
    int bkk = tid >> 3;
    int natp = (tid & 7) * 2;
    uint32_t bsw0 = (uint32_t)(bkk * 256) + ((uint32_t)((natp)     ^ (bkk & 7)) << 4);
    uint32_t bsw1 = (uint32_t)(bkk * 256) + ((uint32_t)((natp + 1) ^ (bkk & 7)) << 4);
    const float* bwp = wo + (size_t)e * I_DIM * H_DIM + (size_t)bkk * H_DIM + n0 + natp * 8;

    float c[4][8][4];
#pragma unroll
    for (int i = 0; i < 4; i++)
#pragma unroll
        for (int j = 0; j < 8; j++)
#pragma unroll
            for (int q = 0; q < 4; q++) c[i][j][q] = 0.f;

    uint4 pah0, pah1;
    float4 pb0a, pb0b, pb1a, pb1b;
#define LDG2(K0) do {                                                        \
    if (av) { pah0 = *(const uint4*)(ah + (size_t)(K0));                     \
              pah1 = *(const uint4*)(ah + (size_t)(K0) + 8); }               \
    else { pah0 = make_uint4(0,0,0,0); pah1 = pah0; }                        \
    pb0a = *(const float4*)(bwp + (size_t)(K0) * H_DIM);                     \
    pb0b = *(const float4*)(bwp + (size_t)(K0) * H_DIM + 4);                 \
    pb1a = *(const float4*)(bwp + (size_t)(K0) * H_DIM + 8);                 \
    pb1b = *(const float4*)(bwp + (size_t)(K0) * H_DIM + 12);                \
} while (0)
#define STS2(BUF) do {                                                       \
    char* s_ = sm[BUF];                                                      \
    *(uint4*)(s_ + asw0) = pah0;                                             \
    *(uint4*)(s_ + asw1) = pah1;                                             \
    uint4 H_;                                                                \
    cvt8(pb0a, pb0b, H_); *(uint4*)(s_ + 4096 + bsw0) = H_;                  \
    cvt8(pb1a, pb1b, H_); *(uint4*)(s_ + 4096 + bsw1) = H_;                  \
} while (0)

    LDG2(0); STS2(0);
    LDG2(16);
    __syncthreads();

    int arow_l = warpM + (lane & 15);
    uint32_t acol_l = (uint32_t)((lane >> 4) * 16);
    int bk_l = (lane & 7) + ((lane >> 3) & 1) * 8;
    int bnat_l = (warpN >> 3) + ((lane >> 4) & 1);

    const int NC = I_DIM / 16;  // 48
    for (int cc = 0; cc < NC; cc++) {
        if (cc + 1 < NC) {
            STS2((cc + 1) % 3);
            if (cc + 2 < NC) LDG2((cc + 2) * 16);
            __syncthreads();
        }
        COMPUTE_STAGE(sbase + (cc % 3) * STAGE_B);
    }
#undef LDG2
#undef STS2

    int gr = lane >> 2, gc = (lane & 3) * 2;
#pragma unroll
    for (int i = 0; i < 4; i++) {
#pragma unroll
        for (int hf = 0; hf < 2; hf++) {
            int r = m0 + warpM + i * 16 + gr + hf * 8;
            if (r < ne) {
                int   t = g_tok[e * T_TOK + r];
                float w = g_wt [e * T_TOK + r];
                float* op = out + (size_t)t * H_DIM + n0 + warpN;
#pragma unroll
                for (int j = 0; j < 8; j++) {
                    atomicAdd(op + j * 8 + gc,     w * c[i][j][2 * hf]);
                    atomicAdd(op + j * 8 + gc + 1, w * c[i][j][2 * hf + 1]);
                }
            }
        }
    }
}

// ---------------------------------------------------------------------------
extern "C" void kernel_launch(void* const* d_in, const int* in_sizes, int n_in,
                              void* d_out, int out_size) {
    const float* x   = (const float*)d_in[0];
    const float* wr  = (const float*)d_in[1];
    const float* wi0 = (const float*)d_in[2];
    const float* wi1 = (const float*)d_in[3];
    const float* wo  = (const float*)d_in[4];
    float* out = (float*)d_out;

    int write_logits = (out_size >= T_TOK * H_DIM + T_TOK * E_NUM) ? 1 : 0;

    cudaMemsetAsync(out, 0, (size_t)T_TOK * H_DIM * sizeof(float));
    k_init<<<1, 32>>>();
    k_router<<<T_TOK / 8, 256>>>(x, wr, out + (size_t)T_TOK * H_DIM, write_logits);

    dim3 g1(T_TOK / 128, I_DIM / 64, E_NUM);    // (32, 12, 8)
    k_mlp1<<<g1, 128>>>(x, wi0, wi1);

    dim3 g2(T_TOK / 128, H_DIM / 128, E_NUM);   // (32, 16, 8)
    k_mlp2<<<g2, 128>>>(wo, out);
}

// round 13
// speedup vs baseline: 1.2869x; 1.2869x over previous
#include <cuda_runtime.h>
#include <cuda_fp16.h>
#include <cstdint>
#include <math.h>

#define T_TOK 4096
#define H_DIM 2048
#define I_DIM 768
#define E_NUM 8

// ---- scratch (device globals; no allocation allowed) ----
__device__ int    g_cnt[E_NUM];
__device__ int    g_tok[E_NUM * T_TOK];
__device__ float  g_wt [E_NUM * T_TOK];
__device__ __half g_acth[(size_t)E_NUM * T_TOK * I_DIM];
__device__ __half g_xh [(size_t)T_TOK * H_DIM];
__device__ __half g_w0h[(size_t)E_NUM * H_DIM * I_DIM];
__device__ __half g_w1h[(size_t)E_NUM * H_DIM * I_DIM];
__device__ __half g_woh[(size_t)E_NUM * I_DIM * H_DIM];

// ============================ helpers ====================================
__device__ __forceinline__ uint32_t smem_u32(const void* p) {
    uint32_t a;
    asm("{ .reg .u64 t; cvta.to.shared.u64 t, %1; cvt.u32.u64 %0, t; }" : "=r"(a) : "l"(p));
    return a;
}
__device__ __forceinline__ void ldm_x4(uint32_t* r, uint32_t a) {
    asm volatile("ldmatrix.sync.aligned.m8n8.x4.shared.b16 {%0,%1,%2,%3}, [%4];"
                 : "=r"(r[0]), "=r"(r[1]), "=r"(r[2]), "=r"(r[3]) : "r"(a));
}
__device__ __forceinline__ void ldm_x4_t(uint32_t* r, uint32_t a) {
    asm volatile("ldmatrix.sync.aligned.m8n8.x4.trans.shared.b16 {%0,%1,%2,%3}, [%4];"
                 : "=r"(r[0]), "=r"(r[1]), "=r"(r[2]), "=r"(r[3]) : "r"(a));
}
__device__ __forceinline__ void mma16816(float* c, const uint32_t* a, uint32_t b0, uint32_t b1) {
    asm volatile("mma.sync.aligned.m16n8k16.row.col.f32.f16.f16.f32 "
                 "{%0,%1,%2,%3}, {%4,%5,%6,%7}, {%8,%9}, {%0,%1,%2,%3};"
                 : "+f"(c[0]), "+f"(c[1]), "+f"(c[2]), "+f"(c[3])
                 : "r"(a[0]), "r"(a[1]), "r"(a[2]), "r"(a[3]), "r"(b0), "r"(b1));
}
__device__ __forceinline__ void cpa16(uint32_t dst, const void* src, int srcsize) {
    asm volatile("cp.async.cg.shared.global [%0], [%1], 16, %2;"
                 :: "r"(dst), "l"(src), "r"(srcsize) : "memory");
}
#define CP_COMMIT() asm volatile("cp.async.commit_group;" ::: "memory")
#define CP_WAIT2()  asm volatile("cp.async.wait_group 2;" ::: "memory")
#define CP_WAIT1()  asm volatile("cp.async.wait_group 1;" ::: "memory")
#define CP_WAIT0()  asm volatile("cp.async.wait_group 0;" ::: "memory")

// ---------------------------------------------------------------------------
__global__ void k_init() { if (threadIdx.x < E_NUM) g_cnt[threadIdx.x] = 0; }

// fp32 -> fp16 for x, wi0, wi1, wo (one launch)
__global__ void k_cvt4(const float* __restrict__ x,  const float* __restrict__ wi0,
                       const float* __restrict__ wi1, const float* __restrict__ wo) {
    const int NX4 = T_TOK * H_DIM / 4;            // 2097152
    const int NW4 = E_NUM * H_DIM * I_DIM / 4;    // 3145728
    int i = blockIdx.x * blockDim.x + threadIdx.x;
    const float* s; __half* d; int j;
    if (i < NX4)                { s = x;   d = g_xh;  j = i; }
    else if (i < NX4 + NW4)     { s = wi0; d = g_w0h; j = i - NX4; }
    else if (i < NX4 + 2 * NW4) { s = wi1; d = g_w1h; j = i - NX4 - NW4; }
    else if (i < NX4 + 3 * NW4) { s = wo;  d = g_woh; j = i - NX4 - 2 * NW4; }
    else return;
    float4 v = ((const float4*)s)[j];
    __half2 h0 = __floats2half2_rn(v.x, v.y);
    __half2 h1 = __floats2half2_rn(v.z, v.w);
    ((__half2*)d)[2 * j]     = h0;
    ((__half2*)d)[2 * j + 1] = h1;
}

// ---------------------------------------------------------------------------
__global__ void k_router(const float* __restrict__ x, const float* __restrict__ wr,
                         float* __restrict__ out_logits, int write_logits) {
    int warp = threadIdx.x >> 5, lane = threadIdx.x & 31;
    int t = blockIdx.x * 8 + warp;
    if (t >= T_TOK) return;
    float acc[E_NUM];
#pragma unroll
    for (int e = 0; e < E_NUM; e++) acc[e] = 0.f;
    const float* xp = x + (size_t)t * H_DIM;
    for (int h = lane; h < H_DIM; h += 32) {
        float xv = xp[h];
        const float* w = wr + (size_t)h * E_NUM;
#pragma unroll
        for (int e = 0; e < E_NUM; e++) acc[e] += xv * w[e];
    }
#pragma unroll
    for (int e = 0; e < E_NUM; e++)
#pragma unroll
        for (int o = 16; o > 0; o >>= 1)
            acc[e] += __shfl_xor_sync(0xffffffffu, acc[e], o);
    if (lane == 0) {
        if (write_logits)
#pragma unroll
            for (int e = 0; e < E_NUM; e++)
                out_logits[(size_t)t * E_NUM + e] = acc[e];
        int i1 = 0;
#pragma unroll
        for (int e = 1; e < E_NUM; e++) if (acc[e] > acc[i1]) i1 = e;
        int i2 = (i1 == 0) ? 1 : 0;
#pragma unroll
        for (int e = 0; e < E_NUM; e++)
            if (e != i1 && acc[e] > acc[i2]) i2 = e;
        float p2 = expf(acc[i2] - acc[i1]);
        float w1 = 1.f / (1.f + p2), w2 = p2 * w1;
        int p;
        p = atomicAdd(&g_cnt[i1], 1);
        g_tok[i1 * T_TOK + p] = t; g_wt[i1 * T_TOK + p] = w1;
        p = atomicAdd(&g_cnt[i2], 1);
        g_tok[i2 * T_TOK + p] = t; g_wt[i2 * T_TOK + p] = w2;
    }
}

// ---------------------------------------------------------------------------
// GEMM geometry: BM=128, BN=256, BK=16, 256 thr, warps 2(M)x4(N), warp 64x64.
// Single-pass fp16. Static smem, 4 stages x 12288B: A 4K | B 8K.
// Fills are pure cp.async (fp16 sources). 1 sync/iter, depth-3 prefetch.
// A rows 32B, swizzle off^(((row>>2)&1)<<4); B rows 512B, ^((k&7)<<4) on
// 16B-unit index.
#define STAGE_B 12288
#define NSTAGE  4

#define COMPUTE_STAGE(SB0)                                                    \
    do {                                                                      \
        uint32_t Af[4][4];                                                    \
        _Pragma("unroll")                                                     \
        for (int i = 0; i < 4; i++) {                                         \
            int row = arow_l + i * 16;                                        \
            uint32_t ad = (SB0) + row * 32 +                                  \
                          (acol_l ^ ((((uint32_t)row >> 2) & 1) << 4));       \
            ldm_x4(Af[i], ad);                                                \
        }                                                                     \
        _Pragma("unroll")                                                     \
        for (int jj = 0; jj < 4; jj++) {                                      \
            uint32_t Bf[4];                                                   \
            uint32_t nat = (uint32_t)(bnat_l + jj * 2);                       \
            uint32_t bd = (SB0) + 4096 + bk_l * 512 +                         \
                          ((nat ^ ((uint32_t)bk_l & 7)) << 4);                \
            ldm_x4_t(Bf, bd);                                                 \
            _Pragma("unroll")                                                 \
            for (int i = 0; i < 4; i++) {                                     \
                mma16816(c[i][jj * 2],     Af[i], Bf[0], Bf[1]);              \
                mma16816(c[i][jj * 2 + 1], Af[i], Bf[2], Bf[3]);              \
            }                                                                 \
        }                                                                     \
    } while (0)

#define PIPE_WAIT(CC, NC)                                                     \
    do {                                                                      \
        int rem_ = (NC) - (CC) - 1;                                           \
        if (rem_ >= 2)      CP_WAIT2();                                       \
        else if (rem_ == 1) CP_WAIT1();                                       \
        else                CP_WAIT0();                                       \
    } while (0)

// GEMM1: per expert, [Ne,H] x [H, 128 gate + 128 up interleaved by 8] -> act
__global__ __launch_bounds__(256, 1)
void k_mlp1() {
    __shared__ __align__(16) char sm[NSTAGE][STAGE_B];
    int e  = blockIdx.z;
    int ne = g_cnt[e];
    int m0 = blockIdx.x * 128;
    if (m0 >= ne) return;
    int i0 = blockIdx.y * 128;   // I columns [i0, i0+128)

    int tid = threadIdx.x, lane = tid & 31, wid = tid >> 5;
    int warpM = (wid >> 2) * 64, warpN = (wid & 3) * 64;
    uint32_t sbase = smem_u32(sm);

    // A fill: 256 threads, one 16B unit each (gathered token rows, fp16 src)
    int ar = tid >> 1;
    uint32_t aswz = (uint32_t)(ar * 32) +
                    (((uint32_t)((tid & 1) * 16)) ^ ((((uint32_t)ar >> 2) & 1) << 4));
    int av16 = ((m0 + ar) < ne) ? 16 : 0;
    const __half* axp = g_xh;
    if (av16) axp = g_xh + (size_t)g_tok[e * T_TOK + m0 + ar] * H_DIM + (tid & 1) * 8;

    // B fill: rows bkk, bkk+8; nat even -> w0h, odd -> w1h; I col = i0+(nat>>1)*8
    int bkk = tid >> 5;          // 0..7
    int nat = tid & 31;
    uint32_t bsw0 = (uint32_t)(bkk * 512) + ((uint32_t)(nat ^ (bkk & 7)) << 4);
    uint32_t bsw1 = bsw0 + 8 * 512;
    size_t wsel = (size_t)e * H_DIM * I_DIM + (size_t)bkk * I_DIM + i0 + (nat >> 1) * 8;
    const __half* bwp = ((nat & 1) ? g_w1h : g_w0h) + wsel;

    float c[4][8][4];
#pragma unroll
    for (int i = 0; i < 4; i++)
#pragma unroll
        for (int j = 0; j < 8; j++)
#pragma unroll
            for (int q = 0; q < 4; q++) c[i][j][q] = 0.f;

#define ISSUE1(S, C) do {                                                    \
    uint32_t s_ = sbase + (S) * STAGE_B;                                     \
    cpa16(s_ + aswz, axp + (size_t)(C) * 16, av16);                          \
    cpa16(s_ + 4096 + bsw0, bwp + (size_t)(C) * 16 * I_DIM, 16);             \
    cpa16(s_ + 4096 + bsw1, bwp + ((size_t)(C) * 16 + 8) * I_DIM, 16);       \
    CP_COMMIT();                                                             \
} while (0)

    ISSUE1(0, 0); ISSUE1(1, 1); ISSUE1(2, 2);

    int arow_l = warpM + (lane & 15);
    uint32_t acol_l = (uint32_t)((lane >> 4) * 16);
    int bk_l = (lane & 7) + ((lane >> 3) & 1) * 8;
    int bnat_l = (warpN >> 3) + ((lane >> 4) & 1);

    const int NC = H_DIM / 16;  // 128
    for (int cc = 0; cc < NC; cc++) {
        PIPE_WAIT(cc, NC);
        __syncthreads();
        if (cc + 3 < NC) ISSUE1((cc + 3) & 3, cc + 3);
        COMPUTE_STAGE(sbase + (cc & 3) * STAGE_B);
    }
#undef ISSUE1

    // Epilogue: accum pairs (2jj, 2jj+1) = (gate, up); silu -> fp16 act.
    int gr = lane >> 2, gc = (lane & 3) * 2;
#pragma unroll
    for (int i = 0; i < 4; i++) {
#pragma unroll
        for (int jj = 0; jj < 4; jj++) {
            int jg = jj * 2, ju = jj * 2 + 1;
            int ic = i0 + ((wid & 3) * 4 + jj) * 8 + gc;
#pragma unroll
            for (int hf = 0; hf < 2; hf++) {
                int slot = m0 + warpM + i * 16 + gr + hf * 8;
                if (slot < ne) {
                    float g0 = c[i][jg][2 * hf], g1 = c[i][jg][2 * hf + 1];
                    float u0 = c[i][ju][2 * hf], u1 = c[i][ju][2 * hf + 1];
                    float a0 = (g0 / (1.f + expf(-g0))) * u0;
                    float a1 = (g1 / (1.f + expf(-g1))) * u1;
                    __half2 hh = __floats2half2_rn(a0, a1);
                    size_t off = ((size_t)e * T_TOK + slot) * I_DIM + ic;
                    *(uint32_t*)(g_acth + off) = *(uint32_t*)&hh;
                }
            }
        }
    }
}

// ---------------------------------------------------------------------------
__global__ __launch_bounds__(256, 1)
void k_mlp2(float* __restrict__ out) {
    __shared__ __align__(16) char sm[NSTAGE][STAGE_B];
    int e  = blockIdx.z;
    int ne = g_cnt[e];
    int m0 = blockIdx.x * 128;
    if (m0 >= ne) return;
    int n0 = blockIdx.y * 256;

    int tid = threadIdx.x, lane = tid & 31, wid = tid >> 5;
    int warpM = (wid >> 2) * 64, warpN = (wid & 3) * 64;
    uint32_t sbase = smem_u32(sm);

    // A fill: fp16 act plane, one 16B unit per thread
    int ar = tid >> 1;
    uint32_t aswz = (uint32_t)(ar * 32) +
                    (((uint32_t)((tid & 1) * 16)) ^ ((((uint32_t)ar >> 2) & 1) << 4));
    int av16 = ((m0 + ar) < ne) ? 16 : 0;
    const __half* ah = g_acth + ((size_t)e * T_TOK + m0 + ar) * I_DIM + (tid & 1) * 8;

    // B fill: woh fp16, rows bkk, bkk+8
    int bkk = tid >> 5;
    int nat = tid & 31;
    uint32_t bsw0 = (uint32_t)(bkk * 512) + ((uint32_t)(nat ^ (bkk & 7)) << 4);
    uint32_t bsw1 = bsw0 + 8 * 512;
    const __half* bwp = g_woh + (size_t)e * I_DIM * H_DIM + (size_t)bkk * H_DIM + n0 + nat * 8;

    float c[4][8][4];
#pragma unroll
    for (int i = 0; i < 4; i++)
#pragma unroll
        for (int j = 0; j < 8; j++)
#pragma unroll
            for (int q = 0; q < 4; q++) c[i][j][q] = 0.f;

#define ISSUE2(S, C) do {                                                    \
    uint32_t s_ = sbase + (S) * STAGE_B;                                     \
    cpa16(s_ + aswz, ah + (size_t)(C) * 16, av16);                           \
    cpa16(s_ + 4096 + bsw0, bwp + (size_t)(C) * 16 * H_DIM, 16);             \
    cpa16(s_ + 4096 + bsw1, bwp + ((size_t)(C) * 16 + 8) * H_DIM, 16);       \
    CP_COMMIT();                                                             \
} while (0)

    ISSUE2(0, 0); ISSUE2(1, 1); ISSUE2(2, 2);

    int arow_l = warpM + (lane & 15);
    uint32_t acol_l = (uint32_t)((lane >> 4) * 16);
    int bk_l = (lane & 7) + ((lane >> 3) & 1) * 8;
    int bnat_l = (warpN >> 3) + ((lane >> 4) & 1);

    const int NC = I_DIM / 16;  // 48
    for (int cc = 0; cc < NC; cc++) {
        PIPE_WAIT(cc, NC);
        __syncthreads();
        if (cc + 3 < NC) ISSUE2((cc + 3) & 3, cc + 3);
        COMPUTE_STAGE(sbase + (cc & 3) * STAGE_B);
    }
#undef ISSUE2

    int gr = lane >> 2, gc = (lane & 3) * 2;
#pragma unroll
    for (int i = 0; i < 4; i++) {
#pragma unroll
        for (int hf = 0; hf < 2; hf++) {
            int r = m0 + warpM + i * 16 + gr + hf * 8;
            if (r < ne) {
                int   t = g_tok[e * T_TOK + r];
                float w = g_wt [e * T_TOK + r];
                float* op = out + (size_t)t * H_DIM + n0 + warpN;
#pragma unroll
                for (int j = 0; j < 8; j++) {
                    atomicAdd(op + j * 8 + gc,     w * c[i][j][2 * hf]);
                    atomicAdd(op + j * 8 + gc + 1, w * c[i][j][2 * hf + 1]);
                }
            }
        }
    }
}

// ---------------------------------------------------------------------------
extern "C" void kernel_launch(void* const* d_in, const int* in_sizes, int n_in,
                              void* d_out, int out_size) {
    const float* x   = (const float*)d_in[0];
    const float* wr  = (const float*)d_in[1];
    const float* wi0 = (const float*)d_in[2];
    const float* wi1 = (const float*)d_in[3];
    const float* wo  = (const float*)d_in[4];
    float* out = (float*)d_out;

    int write_logits = (out_size >= T_TOK * H_DIM + T_TOK * E_NUM) ? 1 : 0;

    cudaMemsetAsync(out, 0, (size_t)T_TOK * H_DIM * sizeof(float));
    k_init<<<1, 32>>>();
    k_router<<<T_TOK / 8, 256>>>(x, wr, out + (size_t)T_TOK * H_DIM, write_logits);

    const int NX4 = T_TOK * H_DIM / 4;
    const int NW4 = E_NUM * H_DIM * I_DIM / 4;
    k_cvt4<<<(NX4 + 3 * NW4 + 255) / 256, 256>>>(x, wi0, wi1, wo);

    dim3 g1(T_TOK / 128, I_DIM / 128, E_NUM);   // (32, 6, 8)
    k_mlp1<<<g1, 256>>>();

    dim3 g2(T_TOK / 128, H_DIM / 256, E_NUM);   // (32, 8, 8)
    k_mlp2<<<g2, 256>>>(out);
}